// round 1
// baseline (speedup 1.0000x reference)
#include <cuda_runtime.h>
#include <math.h>

#define N      4096
#define NDIM   1024
#define NOUT   16
#define DIN    64
#define BK     64          // Cholesky block size
#define NB     (NDIM/BK)   // 16 panel iterations

// ---------------- scratch (device globals; no allocation) ----------------
__device__ float g_F[(size_t)N * NDIM];                 // F = tanh(x Wf), [n][i]
__device__ float g_A[(size_t)NOUT * NDIM * NDIM];       // working copy of P -> L (lower)
__device__ float g_Linv[(size_t)NOUT * NB * BK * BK];   // diag-block inverses [k][jb][r][c]
__device__ float g_Z[(size_t)NOUT * NDIM * N];          // Z = L^{-1} F^T, [k][i][n]

// ---------------- F = tanh(x @ Wf) ----------------
// grid (NDIM/256, N/16), block 256
__global__ __launch_bounds__(256) void k_F(const float* __restrict__ x,
                                           const float* __restrict__ Wf) {
    __shared__ float xs[16][DIN];
    int n0 = blockIdx.y * 16;
    int i  = blockIdx.x * 256 + threadIdx.x;
    for (int t = threadIdx.x; t < 16 * DIN; t += 256)
        xs[t / DIN][t % DIN] = x[(size_t)(n0 + t / DIN) * DIN + (t % DIN)];
    __syncthreads();
    float acc[16];
#pragma unroll
    for (int nn = 0; nn < 16; nn++) acc[nn] = 0.f;
    for (int d = 0; d < DIN; d++) {
        float wf = Wf[(size_t)d * NDIM + i];
#pragma unroll
        for (int nn = 0; nn < 16; nn++) acc[nn] += xs[nn][d] * wf;
    }
#pragma unroll
    for (int nn = 0; nn < 16; nn++)
        g_F[(size_t)(n0 + nn) * NDIM + i] = tanhf(acc[nn]);
}

// ---------------- m = F @ w^T ----------------
// one warp per n; grid N/8, block 256
__global__ __launch_bounds__(256) void k_m(const float* __restrict__ w,
                                           float* __restrict__ out_m) {
    int warp = threadIdx.x >> 5, lane = threadIdx.x & 31;
    int n = blockIdx.x * 8 + warp;
    const float* Frow = &g_F[(size_t)n * NDIM];
    for (int k = 0; k < NOUT; k++) {
        float s = 0.f;
        for (int i = lane; i < NDIM; i += 32) s += Frow[i] * w[(size_t)k * NDIM + i];
#pragma unroll
        for (int o = 16; o > 0; o >>= 1) s += __shfl_down_sync(0xffffffffu, s, o);
        if (lane == 0) out_m[(size_t)n * NOUT + k] = s;
    }
}

// ---------------- copy P -> A, zero s-half of output ----------------
__global__ __launch_bounds__(256) void k_copyP(const float* __restrict__ P,
                                               float* __restrict__ out_s) {
    size_t idx = (size_t)blockIdx.x * 256 + threadIdx.x;
    g_A[idx] = P[idx];
    if (idx < (size_t)N * NOUT) out_s[idx] = 0.f;
}

// ---------------- Cholesky: factor 64x64 diagonal block + invert it ----------------
// grid NOUT, block 128
__global__ __launch_bounds__(128) void k_chol_diag(int jb) {
    __shared__ float D[BK][BK + 1];
    __shared__ float X[BK][BK + 1];
    int k  = blockIdx.x;
    int j0 = jb * BK;
    float* Abase = &g_A[(size_t)k * NDIM * NDIM];
    for (int t = threadIdx.x; t < BK * BK; t += 128)
        D[t / BK][t % BK] = Abase[(size_t)(j0 + t / BK) * NDIM + j0 + (t % BK)];
    __syncthreads();
    // unblocked Cholesky (lower) on the full block (upper stays symmetric, unused)
    for (int j = 0; j < BK; j++) {
        if (threadIdx.x == 0) D[j][j] = sqrtf(D[j][j]);
        __syncthreads();
        float dj = D[j][j];
        for (int r = j + 1 + threadIdx.x; r < BK; r += 128) D[r][j] /= dj;
        __syncthreads();
        int m = BK - 1 - j;
        for (int t = threadIdx.x; t < m * m; t += 128) {
            int r = j + 1 + t / m, c = j + 1 + t % m;
            D[r][c] -= D[r][j] * D[c][j];
        }
        __syncthreads();
    }
    // invert lower triangle: solve L X = I, one column per thread (threads 0..63)
    if (threadIdx.x < BK) {
        int c = threadIdx.x;
        for (int r = 0; r < c; r++) X[r][c] = 0.f;
        X[c][c] = 1.f / D[c][c];
        for (int r = c + 1; r < BK; r++) {
            float ssum = 0.f;
            for (int t = c; t < r; t++) ssum += D[r][t] * X[t][c];
            X[r][c] = -ssum / D[r][r];
        }
    }
    __syncthreads();
    float* Lout = &g_Linv[((size_t)k * NB + jb) * BK * BK];
    for (int t = threadIdx.x; t < BK * BK; t += 128)
        Lout[t] = X[t / BK][t % BK];
}

// ---------------- panel TRSM as GEMM: A_panel <- A_panel @ Linv^T ----------------
// grid (NOUT, nrows/64), block 256
__global__ __launch_bounds__(256) void k_panel(int jb) {
    __shared__ float At[64][65];
    __shared__ float Li[64][65];
    int k = blockIdx.x;
    int j0 = jb * BK;
    int r0 = j0 + BK + blockIdx.y * 64;
    float* Abase = &g_A[(size_t)k * NDIM * NDIM];
    const float* Lbase = &g_Linv[((size_t)k * NB + jb) * BK * BK];
    for (int t = threadIdx.x; t < 64 * 64; t += 256) {
        At[t / 64][t % 64] = Abase[(size_t)(r0 + t / 64) * NDIM + j0 + (t % 64)];
        Li[t / 64][t % 64] = Lbase[t];
    }
    __syncthreads();
    int tr = (threadIdx.x / 16) * 4, tc = (threadIdx.x % 16) * 4;
    float acc[4][4] = {};
    for (int t = 0; t < 64; t++) {
        float a[4], b[4];
#pragma unroll
        for (int u = 0; u < 4; u++) { a[u] = At[tr + u][t]; b[u] = Li[tc + u][t]; }
#pragma unroll
        for (int u = 0; u < 4; u++)
#pragma unroll
            for (int v = 0; v < 4; v++) acc[u][v] += a[u] * b[v];
    }
#pragma unroll
    for (int u = 0; u < 4; u++)
#pragma unroll
        for (int v = 0; v < 4; v++)
            Abase[(size_t)(r0 + tr + u) * NDIM + j0 + tc + v] = acc[u][v];
}

// ---------------- SYRK trailing update (lower tiles): C -= Pan @ Pan^T ----------------
// grid (NOUT, nt*(nt+1)/2), block 256
__global__ __launch_bounds__(256) void k_syrk(int jb) {
    __shared__ float Ar[64][65];
    __shared__ float Ac[64][65];
    int k = blockIdx.x;
    int p = blockIdx.y;
    int rt = 0;
    while ((rt + 1) * (rt + 2) / 2 <= p) rt++;
    int ct = p - rt * (rt + 1) / 2;
    int j0 = jb * BK, j1 = j0 + BK;
    int r0 = j1 + rt * 64, c0 = j1 + ct * 64;
    float* Abase = &g_A[(size_t)k * NDIM * NDIM];
    for (int t = threadIdx.x; t < 64 * 64; t += 256) {
        Ar[t / 64][t % 64] = Abase[(size_t)(r0 + t / 64) * NDIM + j0 + (t % 64)];
        Ac[t / 64][t % 64] = Abase[(size_t)(c0 + t / 64) * NDIM + j0 + (t % 64)];
    }
    __syncthreads();
    int tr = (threadIdx.x / 16) * 4, tc = (threadIdx.x % 16) * 4;
    float acc[4][4] = {};
    for (int t = 0; t < 64; t++) {
        float a[4], b[4];
#pragma unroll
        for (int u = 0; u < 4; u++) { a[u] = Ar[tr + u][t]; b[u] = Ac[tc + u][t]; }
#pragma unroll
        for (int u = 0; u < 4; u++)
#pragma unroll
            for (int v = 0; v < 4; v++) acc[u][v] += a[u] * b[v];
    }
#pragma unroll
    for (int u = 0; u < 4; u++)
#pragma unroll
        for (int v = 0; v < 4; v++) {
            size_t idx = (size_t)(r0 + tr + u) * NDIM + c0 + tc + v;
            Abase[idx] -= acc[u][v];
        }
}

// ---------------- blocked forward substitution step i of Z = L^{-1} F^T ----------------
// T = F^T_i - L[i, 0:i] @ Z[0:i];  Z_i = Linv_ii @ T;  s[n,k] += colnorm^2(Z_i)
// grid (NOUT, N/64), block 256
__global__ __launch_bounds__(256) void k_trsm(int istep) {
    __shared__ float Ta[64][65];   // mainloop: L tile   | epilogue: T
    __shared__ float Tb[64][65];   // mainloop: Z tile   | epilogue: Linv
    __shared__ float red[16][64];
    int k  = blockIdx.x;
    int n0 = blockIdx.y * 64;
    int i0 = istep * BK;
    const float* Abase = &g_A[(size_t)k * NDIM * NDIM];
    const float* Lbase = &g_Linv[((size_t)k * NB + istep) * BK * BK];
    int tr = (threadIdx.x / 16) * 4, tc = (threadIdx.x % 16) * 4;

    // acc[r][n] initialized to F^T  (F[n][i0+r])
    float acc[4][4];
#pragma unroll
    for (int u = 0; u < 4; u++)
#pragma unroll
        for (int v = 0; v < 4; v++)
            acc[u][v] = g_F[(size_t)(n0 + tc + v) * NDIM + i0 + tr + u];

    for (int kk = 0; kk < i0; kk += 64) {
        for (int t = threadIdx.x; t < 64 * 64; t += 256) {
            Ta[t / 64][t % 64] = Abase[(size_t)(i0 + t / 64) * NDIM + kk + (t % 64)];
            Tb[t / 64][t % 64] = g_Z[((size_t)k * NDIM + kk + t / 64) * N + n0 + (t % 64)];
        }
        __syncthreads();
        for (int t = 0; t < 64; t++) {
            float a[4], b[4];
#pragma unroll
            for (int u = 0; u < 4; u++) { a[u] = Ta[tr + u][t]; b[u] = Tb[t][tc + u]; }
#pragma unroll
            for (int u = 0; u < 4; u++)
#pragma unroll
                for (int v = 0; v < 4; v++) acc[u][v] -= a[u] * b[v];
        }
        __syncthreads();
    }

    // epilogue: Z_i = Linv @ T
#pragma unroll
    for (int u = 0; u < 4; u++)
#pragma unroll
        for (int v = 0; v < 4; v++) Ta[tr + u][tc + v] = acc[u][v];
    for (int t = threadIdx.x; t < 64 * 64; t += 256)
        Tb[t / 64][t % 64] = Lbase[t];
    __syncthreads();

    float z[4][4] = {};
    for (int t = 0; t < 64; t++) {
        float a[4], b[4];
#pragma unroll
        for (int u = 0; u < 4; u++) { a[u] = Tb[tr + u][t]; b[u] = Ta[t][tc + u]; }
#pragma unroll
        for (int u = 0; u < 4; u++)
#pragma unroll
            for (int v = 0; v < 4; v++) z[u][v] += a[u] * b[v];
    }
#pragma unroll
    for (int u = 0; u < 4; u++)
#pragma unroll
        for (int v = 0; v < 4; v++)
            g_Z[((size_t)k * NDIM + i0 + tr + u) * N + n0 + tc + v] = z[u][v];

    // s partial: sum over the 64 rows of this block
    float p4[4];
#pragma unroll
    for (int v = 0; v < 4; v++) {
        float s = 0.f;
#pragma unroll
        for (int u = 0; u < 4; u++) s += z[u][v] * z[u][v];
        p4[v] = s;
    }
    int rg = threadIdx.x / 16;
#pragma unroll
    for (int v = 0; v < 4; v++) red[rg][tc + v] = p4[v];
    __syncthreads();
    if (threadIdx.x < 64) {
        float tot = 0.f;
#pragma unroll
        for (int g = 0; g < 16; g++) tot += red[g][threadIdx.x];
        // out_s accumulation: unique (k, n) per CTA within a launch; launches ordered
        float* out_s = (float*)0;  // patched below via constant? -> use global pointer arg instead
        (void)out_s;
        // stored via g_Z? No: write through the pointer passed in .param (see wrapper)
        // -- handled by k_trsm_out below
        red[0][threadIdx.x] = tot;  // stash for the writing thread (same thread) -- direct write:
    }
    __syncthreads();
    if (threadIdx.x < 64) {
        extern __device__ float g_sout[];  // not used
    }
}

// NOTE: the above accumulation needs the output pointer; simpler to pass it in.
// Redefine the TRSM kernel properly with the output pointer parameter.
__global__ __launch_bounds__(256) void k_trsm2(int istep, float* __restrict__ out_s) {
    __shared__ float Ta[64][65];
    __shared__ float Tb[64][65];
    __shared__ float red[16][64];
    int k  = blockIdx.x;
    int n0 = blockIdx.y * 64;
    int i0 = istep * BK;
    const float* Abase = &g_A[(size_t)k * NDIM * NDIM];
    const float* Lbase = &g_Linv[((size_t)k * NB + istep) * BK * BK];
    int tr = (threadIdx.x / 16) * 4, tc = (threadIdx.x % 16) * 4;

    float acc[4][4];
#pragma unroll
    for (int u = 0; u < 4; u++)
#pragma unroll
        for (int v = 0; v < 4; v++)
            acc[u][v] = g_F[(size_t)(n0 + tc + v) * NDIM + i0 + tr + u];

    for (int kk = 0; kk < i0; kk += 64) {
        for (int t = threadIdx.x; t < 64 * 64; t += 256) {
            Ta[t / 64][t % 64] = Abase[(size_t)(i0 + t / 64) * NDIM + kk + (t % 64)];
            Tb[t / 64][t % 64] = g_Z[((size_t)k * NDIM + kk + t / 64) * N + n0 + (t % 64)];
        }
        __syncthreads();
        for (int t = 0; t < 64; t++) {
            float a[4], b[4];
#pragma unroll
            for (int u = 0; u < 4; u++) { a[u] = Ta[tr + u][t]; b[u] = Tb[t][tc + u]; }
#pragma unroll
            for (int u = 0; u < 4; u++)
#pragma unroll
                for (int v = 0; v < 4; v++) acc[u][v] -= a[u] * b[v];
        }
        __syncthreads();
    }

#pragma unroll
    for (int u = 0; u < 4; u++)
#pragma unroll
        for (int v = 0; v < 4; v++) Ta[tr + u][tc + v] = acc[u][v];
    for (int t = threadIdx.x; t < 64 * 64; t += 256)
        Tb[t / 64][t % 64] = Lbase[t];
    __syncthreads();

    float z[4][4] = {};
    for (int t = 0; t < 64; t++) {
        float a[4], b[4];
#pragma unroll
        for (int u = 0; u < 4; u++) { a[u] = Tb[tr + u][t]; b[u] = Ta[t][tc + u]; }
#pragma unroll
        for (int u = 0; u < 4; u++)
#pragma unroll
            for (int v = 0; v < 4; v++) z[u][v] += a[u] * b[v];
    }
#pragma unroll
    for (int u = 0; u < 4; u++)
#pragma unroll
        for (int v = 0; v < 4; v++)
            g_Z[((size_t)k * NDIM + i0 + tr + u) * N + n0 + tc + v] = z[u][v];

    float p4[4];
#pragma unroll
    for (int v = 0; v < 4; v++) {
        float s = 0.f;
#pragma unroll
        for (int u = 0; u < 4; u++) s += z[u][v] * z[u][v];
        p4[v] = s;
    }
    int rg = threadIdx.x / 16;
#pragma unroll
    for (int v = 0; v < 4; v++) red[rg][tc + v] = p4[v];
    __syncthreads();
    if (threadIdx.x < 64) {
        float tot = 0.f;
#pragma unroll
        for (int g = 0; g < 16; g++) tot += red[g][threadIdx.x];
        out_s[(size_t)(n0 + threadIdx.x) * NOUT + k] += tot;
    }
}

// ---------------- launch ----------------
extern "C" void kernel_launch(void* const* d_in, const int* in_sizes, int n_in,
                              void* d_out, int out_size) {
    const float* x  = (const float*)d_in[0];   // (N, DIN)
    const float* Wf = (const float*)d_in[1];   // (DIN, NDIM)
    const float* w  = (const float*)d_in[2];   // (NOUT, NDIM, 1)
    const float* P  = (const float*)d_in[3];   // (NOUT, NDIM, NDIM)
    float* out   = (float*)d_out;
    float* out_m = out;                         // (N, NOUT)
    float* out_s = out + (size_t)N * NOUT;      // (N, NOUT)

    k_F<<<dim3(NDIM / 256, N / 16), 256>>>(x, Wf);
    k_m<<<N / 8, 256>>>(w, out_m);
    k_copyP<<<(unsigned)((size_t)NOUT * NDIM * NDIM / 256), 256>>>(P, out_s);

    for (int jb = 0; jb < NB; jb++) {
        k_chol_diag<<<NOUT, 128>>>(jb);
        int nrows = NDIM - BK * (jb + 1);
        if (nrows > 0) {
            k_panel<<<dim3(NOUT, nrows / 64), 256>>>(jb);
            int nt = nrows / 64;
            k_syrk<<<dim3(NOUT, nt * (nt + 1) / 2), 256>>>(jb);
        }
    }
    for (int i = 0; i < NB; i++) {
        k_trsm2<<<dim3(NOUT, N / 64), 256>>>(i, out_s);
    }
}